// round 12
// baseline (speedup 1.0000x reference)
#include <cuda_runtime.h>
#include <math.h>
#include <stddef.h>
#include <stdint.h>

// Problem constants
#define B_    2
#define S_    2048
#define D_    1024
#define H_    16
#define DK_   64
#define DFF_  4096
#define M_    (B_ * S_)          // 4096 rows
#define EPS_  1e-6f
#define D3_   (3 * D_)           // 3072

// ---------------------------------------------------------------------------
// Scratch (device globals: allocation-free workaround per harness rules)
// ---------------------------------------------------------------------------
__device__ float g_n   [(size_t)M_ * D_];
__device__ float g_qkv [(size_t)M_ * D3_];     // q|k|v interleaved per row
__device__ float g_ctx [(size_t)M_ * D_];
__device__ float g_x1  [(size_t)M_ * D_];
__device__ float g_n2  [(size_t)M_ * D_];
__device__ float g_ff1 [(size_t)M_ * DFF_];
// rounded (tf32-exact) weights: wqkv(concat [K,3D]) | wo | w1 | w2
__device__ float g_wr  [(size_t)(D_ * D3_ + D_ * D_ + 2 * D_ * DFF_)];
__device__ float g_bqkv[D3_];

// ---------------------------------------------------------------------------
// helpers
// ---------------------------------------------------------------------------
__device__ __forceinline__ float rnd_tf32(float x) {
    uint32_t u;
    asm("cvt.rna.tf32.f32 %0, %1;" : "=r"(u) : "f"(x));
    return __uint_as_float(u);
}

__device__ __forceinline__ void mma_tf32(float* c, const uint32_t* a, const uint32_t* b) {
    asm volatile(
        "mma.sync.aligned.m16n8k8.row.col.f32.tf32.tf32.f32 "
        "{%0,%1,%2,%3}, {%4,%5,%6,%7}, {%8,%9}, {%0,%1,%2,%3};"
        : "+f"(c[0]), "+f"(c[1]), "+f"(c[2]), "+f"(c[3])
        : "r"(a[0]), "r"(a[1]), "r"(a[2]), "r"(a[3]), "r"(b[0]), "r"(b[1]));
}

__device__ __forceinline__ void cp16(float* s, const float* g) {
    uint32_t sa = (uint32_t)__cvta_generic_to_shared(s);
    asm volatile("cp.async.cg.shared.global [%0], [%1], 16;\n" :: "r"(sa), "l"(g));
}
__device__ __forceinline__ void cp_commit() {
    asm volatile("cp.async.commit_group;\n");
}
template<int N>
__device__ __forceinline__ void cp_wait() {
    asm volatile("cp.async.wait_group %0;\n" :: "n"(N));
}

// ---------------------------------------------------------------------------
// Weight pre-round kernels
// ---------------------------------------------------------------------------
__global__ void roundw_kernel(const float* __restrict__ in, float* __restrict__ out,
                              int n4) {
    int i = blockIdx.x * blockDim.x + threadIdx.x;
    int stride = gridDim.x * blockDim.x;
    for (; i < n4; i += stride) {
        float4 v = ((const float4*)in)[i];
        v.x = rnd_tf32(v.x); v.y = rnd_tf32(v.y);
        v.z = rnd_tf32(v.z); v.w = rnd_tf32(v.w);
        ((float4*)out)[i] = v;
    }
}

// wqkv[k][n] (n<1024: wq, <2048: wk, else wv), rounded; also bias concat.
__global__ void round_qkv_kernel(const float* __restrict__ wq,
                                 const float* __restrict__ wk,
                                 const float* __restrict__ wv,
                                 const float* __restrict__ bq,
                                 const float* __restrict__ bk,
                                 const float* __restrict__ bv,
                                 float* __restrict__ wout,
                                 float* __restrict__ bout) {
    const int CH = D3_ / 4;                 // 768 float4 per row
    int i = blockIdx.x * blockDim.x + threadIdx.x;
    int stride = gridDim.x * blockDim.x;
    for (; i < D_ * CH; i += stride) {
        int k = i / CH, c4 = i % CH;
        int n = c4 * 4;
        const float* src = (n < D_)     ? (wq + (size_t)k * D_ + n)
                         : (n < 2 * D_) ? (wk + (size_t)k * D_ + n - D_)
                                        : (wv + (size_t)k * D_ + n - 2 * D_);
        float4 v = *(const float4*)src;
        v.x = rnd_tf32(v.x); v.y = rnd_tf32(v.y);
        v.z = rnd_tf32(v.z); v.w = rnd_tf32(v.w);
        ((float4*)wout)[i] = v;
    }
    int t = blockIdx.x * blockDim.x + threadIdx.x;
    if (t < D3_) {
        bout[t] = (t < D_) ? bq[t] : (t < 2 * D_) ? bk[t - D_] : bv[t - 2 * D_];
    }
}

// ---------------------------------------------------------------------------
// tf32 tensor-core GEMM: 3-stage cp.async pipeline, BK=16, XOR-swizzled
// pad-free smem (exactly 48KB static), ONE __syncthreads per k-tile.
// __launch_bounds__(128, 2): 256 regs/thread — acc[4][8][4] (128 regs) must
// NOT spill (the (128,4) variant capped regs at 128 and spilled: 2.4x slower).
// 128 threads = 4 warps (2x2), WM=64, WN=64.
//   A swizzle: elem (r, c) at r*16 + (c ^ (4*((r>>1)&3)))
//   B swizzle: elem (kr, n) at kr*128 + (n ^ (8*(kr&3)))
// EPI: 0=bias, 1=bias+relu, 2=bias+residual
// RND: 1 = round output to tf32 (feeds later MMA), 0 = exact fp32.
// ---------------------------------------------------------------------------
template<int EPI, int RND>
__global__ void __launch_bounds__(128, 2)
mma_gemm(const float* __restrict__ Ag, const float* __restrict__ Bg,
         const float* __restrict__ bias, const float* __restrict__ Res,
         float* __restrict__ Cg,
         int M, int N, int K, int lda, int ldb, int ldc) {
    constexpr int BM = 128, BN = 128, BK = 16;
    constexpr int MA = 4, NA = 8;          // WM=64 (4 m16), WN=64 (8 n8)
    constexpr int ASZ = BM * BK;           // 2048 floats per stage
    constexpr int BSZ = BK * BN;           // 2048 floats per stage

    __shared__ float As[3][ASZ];
    __shared__ float Bs[3][BSZ];

    int tid = threadIdx.x;
    int lane = tid & 31, wid = tid >> 5;
    int wm = wid >> 1, wn = wid & 1;
    int gid = lane >> 2, tg = lane & 3;
    int bx = blockIdx.x, by = blockIdx.y;

    const float* A = Ag + (size_t)(by * BM) * lda;
    const float* Bp = Bg;

    float acc[MA][NA][4] = {};

    // per-thread swizzle constants for fragment reads
    const int swa = 4 * (gid >> 1);        // A col swizzle (rows m, m+8 share it)
    const int swb = 8 * tg;                // B col swizzle (rows ks+tg, +4 share it)

    // ---- stage loader: issue cp.async for k-tile kt into stage st ----
    auto load_stage = [&](int kt, int st) {
        float* as = As[st];
        float* bs = Bs[st];
        int k0 = kt * BK;
        #pragma unroll
        for (int i = tid; i < BM * BK / 4; i += 128) {      // 512 chunks, 4 iters
            int r = i >> 2, q = (i & 3) << 2;
            cp16(as + r * 16 + (q ^ (4 * ((r >> 1) & 3))),
                 A + (size_t)r * lda + k0 + q);
        }
        #pragma unroll
        for (int i = tid; i < BK * BN / 4; i += 128) {      // 512 chunks, 4 iters
            int kr = i >> 5, q = (i & 31) << 2;
            cp16(bs + kr * 128 + (q ^ (8 * (kr & 3))),
                 Bp + (size_t)(k0 + kr) * ldb + bx * BN + q);
        }
        cp_commit();
    };

    int tiles = K / BK;
    load_stage(0, 0);
    load_stage(1, 1);

    for (int t = 0; t < tiles; t++) {
        if (t + 1 < tiles) cp_wait<1>(); else cp_wait<0>();
        __syncthreads();                       // stage t visible; prior reads done
        if (t + 2 < tiles) load_stage(t + 2, (t + 2) % 3);

        const float* as = As[t % 3];
        const float* bs = Bs[t % 3];
        #pragma unroll
        for (int ks = 0; ks < BK; ks += 8) {
            uint32_t af[MA][4], bf[NA][2];
            int c0 = (ks + tg) ^ swa;
            int c1 = (ks + tg + 4) ^ swa;
            #pragma unroll
            for (int ma = 0; ma < MA; ma++) {
                int m = wm * 64 + ma * 16 + gid;
                af[ma][0] = __float_as_uint(as[m * 16 + c0]);
                af[ma][1] = __float_as_uint(as[(m + 8) * 16 + c0]);
                af[ma][2] = __float_as_uint(as[m * 16 + c1]);
                af[ma][3] = __float_as_uint(as[(m + 8) * 16 + c1]);
            }
            int rb0 = (ks + tg) * 128, rb1 = (ks + tg + 4) * 128;
            #pragma unroll
            for (int na = 0; na < NA; na++) {
                int n = (wn * 64 + na * 8 + gid) ^ swb;
                bf[na][0] = __float_as_uint(bs[rb0 + n]);
                bf[na][1] = __float_as_uint(bs[rb1 + n]);
            }
            #pragma unroll
            for (int ma = 0; ma < MA; ma++)
                #pragma unroll
                for (int na = 0; na < NA; na++)
                    mma_tf32(acc[ma][na], af[ma], bf[na]);
        }
    }

    // ---- epilogue ----
    #pragma unroll
    for (int ma = 0; ma < MA; ma++) {
        #pragma unroll
        for (int na = 0; na < NA; na++) {
            int r = by * BM + wm * 64 + ma * 16 + gid;
            int c = bx * BN + wn * 64 + na * 8 + tg * 2;
            float o0 = acc[ma][na][0], o1 = acc[ma][na][1];
            float o2 = acc[ma][na][2], o3 = acc[ma][na][3];
            {
                float b0 = bias[c], b1 = bias[c + 1];
                o0 += b0; o1 += b1; o2 += b0; o3 += b1;
            }
            if (EPI == 1) {
                o0 = fmaxf(o0, 0.f); o1 = fmaxf(o1, 0.f);
                o2 = fmaxf(o2, 0.f); o3 = fmaxf(o3, 0.f);
            }
            if (EPI == 2) {
                const float* rp0 = Res + (size_t)r * ldc + c;
                const float* rp1 = Res + (size_t)(r + 8) * ldc + c;
                o0 += rp0[0]; o1 += rp0[1];
                o2 += rp1[0]; o3 += rp1[1];
            }
            if (RND) {
                o0 = rnd_tf32(o0); o1 = rnd_tf32(o1);
                o2 = rnd_tf32(o2); o3 = rnd_tf32(o3);
            }
            float2 p0 = {o0, o1}, p1 = {o2, o3};
            *(float2*)(Cg + (size_t)r * ldc + c) = p0;
            *(float2*)(Cg + (size_t)(r + 8) * ldc + c) = p1;
        }
    }
}

// ---------------------------------------------------------------------------
// Flash attention over interleaved qkv buffer (row stride 3D).
// Grid: (S/64 q-tiles, B*H). 128 threads = 4 warps (2 along M, 2 along N).
// K and V issued as separate cp.async groups: V load overlaps QK^T+softmax.
// Full mask row preloaded once. Online softmax, reference semantics.
// ---------------------------------------------------------------------------
__global__ void __launch_bounds__(128, 2)
flash_attn_kernel(const float* __restrict__ qkvg, const int* __restrict__ maskg,
                  float* __restrict__ ctxg) {
    __shared__ float sKP[64 * 68];     // K tile, then P tile
    __shared__ float sV [64 * 72];     // V tile
    __shared__ int   sMask[S_];        // full mask row (8KB)
    __shared__ float sRedM[2][64];
    __shared__ float sRedS[2][64];

    int tid = threadIdx.x;
    int lane = tid & 31, wid = tid >> 5;
    int wm = wid >> 1, wn = wid & 1;
    int gid = lane >> 2, tg = lane & 3;
    int qt = blockIdx.x, z = blockIdx.y;
    int bb = z >> 4, hh = z & 15;

    const size_t SD3 = (size_t)S_ * D3_;
    const float* qp = qkvg + bb * SD3 + hh * DK_ + (size_t)(qt * 64) * D3_;
    const float* kp = qkvg + bb * SD3 + D_ + hh * DK_;
    const float* vp = qkvg + bb * SD3 + 2 * D_ + hh * DK_;

    // ---- preload full mask row ----
    #pragma unroll
    for (int i = tid; i < S_ / 4; i += 128)
        ((int4*)sMask)[i] = ((const int4*)(maskg + bb * S_))[i];

    // ---- Q fragments ----
    uint32_t qf[2][8][4];
    #pragma unroll
    for (int ma = 0; ma < 2; ma++) {
        int r0 = wm * 32 + ma * 16 + gid;
        #pragma unroll
        for (int ks = 0; ks < 8; ks++) {
            int c0 = ks * 8 + tg;
            qf[ma][ks][0] = __float_as_uint(qp[(size_t)r0 * D3_ + c0]);
            qf[ma][ks][1] = __float_as_uint(qp[(size_t)(r0 + 8) * D3_ + c0]);
            qf[ma][ks][2] = __float_as_uint(qp[(size_t)r0 * D3_ + c0 + 4]);
            qf[ma][ks][3] = __float_as_uint(qp[(size_t)(r0 + 8) * D3_ + c0 + 4]);
        }
    }

    float oacc[2][4][4] = {};
    float m_run[2][2], l_run[2][2];
    #pragma unroll
    for (int ma = 0; ma < 2; ma++)
        #pragma unroll
        for (int h = 0; h < 2; h++) { m_run[ma][h] = -INFINITY; l_run[ma][h] = 0.f; }

    for (int kt = 0; kt < S_ / 64; kt++) {
        int k0 = kt * 64;
        // ---- K group, then V group (separate commits) ----
        #pragma unroll
        for (int i = tid; i < 1024; i += 128) {
            int n = i >> 4, q4 = (i & 15) << 2;
            cp16(&sKP[n * 68 + q4], kp + (size_t)(k0 + n) * D3_ + q4);
        }
        cp_commit();
        #pragma unroll
        for (int i = tid; i < 1024; i += 128) {
            int n = i >> 4, q4 = (i & 15) << 2;
            cp16(&sV[n * 72 + q4], vp + (size_t)(k0 + n) * D3_ + q4);
        }
        cp_commit();
        cp_wait<1>();          // K complete; V may still be in flight
        __syncthreads();

        // ---- S = Q @ K^T ----
        float sacc[2][4][4] = {};
        #pragma unroll
        for (int ks = 0; ks < 8; ks++) {
            uint32_t kf[4][2];
            #pragma unroll
            for (int na = 0; na < 4; na++) {
                int n = wn * 32 + na * 8 + gid;
                kf[na][0] = __float_as_uint(sKP[n * 68 + ks * 8 + tg]);
                kf[na][1] = __float_as_uint(sKP[n * 68 + ks * 8 + tg + 4]);
            }
            #pragma unroll
            for (int ma = 0; ma < 2; ma++)
                #pragma unroll
                for (int na = 0; na < 4; na++)
                    mma_tf32(sacc[ma][na], qf[ma][ks], kf[na]);
        }

        // ---- mask + scale + tile row-max ----
        float tmax[2][2] = {{-INFINITY, -INFINITY}, {-INFINITY, -INFINITY}};
        #pragma unroll
        for (int ma = 0; ma < 2; ma++)
            #pragma unroll
            for (int na = 0; na < 4; na++) {
                int cb = wn * 32 + na * 8 + 2 * tg;
                int mk0 = sMask[k0 + cb], mk1 = sMask[k0 + cb + 1];
                float s0 = mk0 ? sacc[ma][na][0] * 0.125f : -1e9f;
                float s1 = mk1 ? sacc[ma][na][1] * 0.125f : -1e9f;
                float s2 = mk0 ? sacc[ma][na][2] * 0.125f : -1e9f;
                float s3 = mk1 ? sacc[ma][na][3] * 0.125f : -1e9f;
                sacc[ma][na][0] = s0; sacc[ma][na][1] = s1;
                sacc[ma][na][2] = s2; sacc[ma][na][3] = s3;
                tmax[ma][0] = fmaxf(tmax[ma][0], fmaxf(s0, s1));
                tmax[ma][1] = fmaxf(tmax[ma][1], fmaxf(s2, s3));
            }
        #pragma unroll
        for (int ma = 0; ma < 2; ma++)
            #pragma unroll
            for (int h = 0; h < 2; h++) {
                float v = tmax[ma][h];
                v = fmaxf(v, __shfl_xor_sync(0xffffffffu, v, 1));
                v = fmaxf(v, __shfl_xor_sync(0xffffffffu, v, 2));
                tmax[ma][h] = v;
            }
        if (tg == 0) {
            #pragma unroll
            for (int ma = 0; ma < 2; ma++) {
                sRedM[wn][wm * 32 + ma * 16 + gid]     = tmax[ma][0];
                sRedM[wn][wm * 32 + ma * 16 + gid + 8] = tmax[ma][1];
            }
        }
        __syncthreads();   // K consumed + maxes visible

        // ---- online stats, exp, write P (overwrites K buffer) ----
        float mnew[2][2], fsc[2][2], psum[2][2];
        #pragma unroll
        for (int ma = 0; ma < 2; ma++)
            #pragma unroll
            for (int h = 0; h < 2; h++) {
                int row = wm * 32 + ma * 16 + gid + h * 8;
                float mt = fmaxf(sRedM[0][row], sRedM[1][row]);
                float mn = fmaxf(m_run[ma][h], mt);
                mnew[ma][h] = mn;
                fsc[ma][h] = __expf(m_run[ma][h] - mn);
                psum[ma][h] = 0.f;
            }
        #pragma unroll
        for (int ma = 0; ma < 2; ma++) {
            int r0 = wm * 32 + ma * 16 + gid;
            #pragma unroll
            for (int na = 0; na < 4; na++) {
                int cb = wn * 32 + na * 8 + 2 * tg;
                float p0 = __expf(sacc[ma][na][0] - mnew[ma][0]);
                float p1 = __expf(sacc[ma][na][1] - mnew[ma][0]);
                float p2 = __expf(sacc[ma][na][2] - mnew[ma][1]);
                float p3 = __expf(sacc[ma][na][3] - mnew[ma][1]);
                psum[ma][0] += p0 + p1;
                psum[ma][1] += p2 + p3;
                sKP[r0 * 68 + cb]           = rnd_tf32(p0);
                sKP[r0 * 68 + cb + 1]       = rnd_tf32(p1);
                sKP[(r0 + 8) * 68 + cb]     = rnd_tf32(p2);
                sKP[(r0 + 8) * 68 + cb + 1] = rnd_tf32(p3);
            }
        }
        #pragma unroll
        for (int ma = 0; ma < 2; ma++)
            #pragma unroll
            for (int h = 0; h < 2; h++) {
                float v = psum[ma][h];
                v += __shfl_xor_sync(0xffffffffu, v, 1);
                v += __shfl_xor_sync(0xffffffffu, v, 2);
                psum[ma][h] = v;
            }
        if (tg == 0) {
            #pragma unroll
            for (int ma = 0; ma < 2; ma++) {
                sRedS[wn][wm * 32 + ma * 16 + gid]     = psum[ma][0];
                sRedS[wn][wm * 32 + ma * 16 + gid + 8] = psum[ma][1];
            }
        }
        cp_wait<0>();      // V complete (per-thread) before barrier
        __syncthreads();   // P + sums + V visible

        #pragma unroll
        for (int ma = 0; ma < 2; ma++)
            #pragma unroll
            for (int h = 0; h < 2; h++) {
                int row = wm * 32 + ma * 16 + gid + h * 8;
                l_run[ma][h] = l_run[ma][h] * fsc[ma][h]
                             + (sRedS[0][row] + sRedS[1][row]);
                m_run[ma][h] = mnew[ma][h];
            }
        #pragma unroll
        for (int ma = 0; ma < 2; ma++)
            #pragma unroll
            for (int na = 0; na < 4; na++) {
                oacc[ma][na][0] *= fsc[ma][0];
                oacc[ma][na][1] *= fsc[ma][0];
                oacc[ma][na][2] *= fsc[ma][1];
                oacc[ma][na][3] *= fsc[ma][1];
            }

        // ---- O += P @ V ----
        #pragma unroll
        for (int ks = 0; ks < 8; ks++) {
            uint32_t af[2][4], vf[4][2];
            #pragma unroll
            for (int ma = 0; ma < 2; ma++) {
                int m0 = wm * 32 + ma * 16 + gid;
                af[ma][0] = __float_as_uint(sKP[m0 * 68 + ks * 8 + tg]);
                af[ma][1] = __float_as_uint(sKP[(m0 + 8) * 68 + ks * 8 + tg]);
                af[ma][2] = __float_as_uint(sKP[m0 * 68 + ks * 8 + tg + 4]);
                af[ma][3] = __float_as_uint(sKP[(m0 + 8) * 68 + ks * 8 + tg + 4]);
            }
            #pragma unroll
            for (int na = 0; na < 4; na++) {
                int n = wn * 32 + na * 8 + gid;
                vf[na][0] = __float_as_uint(sV[(ks * 8 + tg) * 72 + n]);
                vf[na][1] = __float_as_uint(sV[(ks * 8 + tg + 4) * 72 + n]);
            }
            #pragma unroll
            for (int ma = 0; ma < 2; ma++)
                #pragma unroll
                for (int na = 0; na < 4; na++)
                    mma_tf32(oacc[ma][na], af[ma], vf[na]);
        }
        __syncthreads();   // P, V consumed before next-iter overwrite
    }

    // ---- epilogue: ctx = O / l, rna-rounded (feeds O-proj MMA) ----
    float* cp_ = ctxg + bb * (size_t)S_ * D_ + hh * DK_;
    #pragma unroll
    for (int ma = 0; ma < 2; ma++) {
        int r0 = qt * 64 + wm * 32 + ma * 16 + gid;
        float inv0 = 1.0f / l_run[ma][0];
        float inv1 = 1.0f / l_run[ma][1];
        #pragma unroll
        for (int na = 0; na < 4; na++) {
            int c = wn * 32 + na * 8 + 2 * tg;
            float2 p0 = {rnd_tf32(oacc[ma][na][0] * inv0),
                         rnd_tf32(oacc[ma][na][1] * inv0)};
            float2 p1 = {rnd_tf32(oacc[ma][na][2] * inv1),
                         rnd_tf32(oacc[ma][na][3] * inv1)};
            *(float2*)(cp_ + (size_t)r0 * D_ + c) = p0;
            *(float2*)(cp_ + (size_t)(r0 + 8) * D_ + c) = p1;
        }
    }
}

// ---------------------------------------------------------------------------
// Block-wide allreduce (256 threads = 8 warps)
// ---------------------------------------------------------------------------
__device__ __forceinline__ float allreduce_sum(float v, float* sh) {
    #pragma unroll
    for (int o = 16; o > 0; o >>= 1) v += __shfl_xor_sync(0xffffffffu, v, o);
    int lane = threadIdx.x & 31, wid = threadIdx.x >> 5;
    if (lane == 0) sh[wid] = v;
    __syncthreads();
    if (wid == 0) {
        float r = sh[lane & 7];
        #pragma unroll
        for (int o = 4; o > 0; o >>= 1) r += __shfl_xor_sync(0xffffffffu, r, o);
        if (lane == 0) sh[0] = r;
    }
    __syncthreads();
    float r = sh[0];
    __syncthreads();
    return r;
}

// ---------------------------------------------------------------------------
// LayerNorm: one block (256 thr) per row of D=1024. ddof=1, eps on std.
// float4 I/O; output rounded to tf32 (it only feeds MMAs).
// ---------------------------------------------------------------------------
__global__ void layernorm_kernel(const float* __restrict__ x,
                                 const float* __restrict__ alpha,
                                 const float* __restrict__ beta,
                                 float* __restrict__ out) {
    __shared__ float sh[32];
    size_t row = blockIdx.x;
    const float4 v = ((const float4*)(x + row * D_))[threadIdx.x];
    float s = v.x + v.y + v.z + v.w;
    s = allreduce_sum(s, sh);
    float mean = s * (1.0f / D_);
    float dx = v.x - mean, dy = v.y - mean, dz = v.z - mean, dw = v.w - mean;
    float var = dx * dx + dy * dy + dz * dz + dw * dw;
    var = allreduce_sum(var, sh) * (1.0f / (D_ - 1));   // Bessel correction
    float scale = alpha[0] / (sqrtf(var) + EPS_);       // eps added to std
    float bias = beta[0];
    float4 o;
    o.x = rnd_tf32(dx * scale + bias);
    o.y = rnd_tf32(dy * scale + bias);
    o.z = rnd_tf32(dz * scale + bias);
    o.w = rnd_tf32(dw * scale + bias);
    ((float4*)(out + row * D_))[threadIdx.x] = o;
}

// ---------------------------------------------------------------------------
// Launch — no attribute calls, all static smem, capture-safe.
// ---------------------------------------------------------------------------
extern "C" void kernel_launch(void* const* d_in, const int* in_sizes, int n_in,
                              void* d_out, int out_size) {
    const float* x    = (const float*)d_in[0];
    const int*   mask = (const int*)  d_in[1];
    const float* wq   = (const float*)d_in[2];
    const float* bq   = (const float*)d_in[3];
    const float* wk   = (const float*)d_in[4];
    const float* bk   = (const float*)d_in[5];
    const float* wv   = (const float*)d_in[6];
    const float* bv   = (const float*)d_in[7];
    const float* wo   = (const float*)d_in[8];
    const float* bo   = (const float*)d_in[9];
    const float* w1   = (const float*)d_in[10];
    const float* b1   = (const float*)d_in[11];
    const float* w2   = (const float*)d_in[12];
    const float* b2   = (const float*)d_in[13];
    const float* a1   = (const float*)d_in[14];
    const float* g1   = (const float*)d_in[15];
    const float* a2   = (const float*)d_in[16];
    const float* g2   = (const float*)d_in[17];
    float* out = (float*)d_out;

    float *n_, *qkv_, *ctx_, *x1_, *n2_, *ff1_, *wr_, *bqkv_;
    cudaGetSymbolAddress((void**)&n_,    g_n);
    cudaGetSymbolAddress((void**)&qkv_,  g_qkv);
    cudaGetSymbolAddress((void**)&ctx_,  g_ctx);
    cudaGetSymbolAddress((void**)&x1_,   g_x1);
    cudaGetSymbolAddress((void**)&n2_,   g_n2);
    cudaGetSymbolAddress((void**)&ff1_,  g_ff1);
    cudaGetSymbolAddress((void**)&wr_,   g_wr);
    cudaGetSymbolAddress((void**)&bqkv_, g_bqkv);

    const long DD = (long)D_ * D_;
    float* wqkvr = wr_;                              // [K=1024, 3072]
    float* wor   = wr_ + (long)D_ * D3_;
    float* w1r   = wor + DD;
    float* w2r   = w1r + (long)D_ * DFF_;

    // ---- pre-round weights to tf32 (exact MMA inputs) ----
    round_qkv_kernel<<<512, 256>>>(wq, wk, wv, bq, bk, bv, wqkvr, bqkv_);
    roundw_kernel<<<512, 256>>>(wo, wor, (int)(DD / 4));
    roundw_kernel<<<512, 256>>>(w1, w1r, (int)((long)D_ * DFF_ / 4));
    roundw_kernel<<<512, 256>>>(w2, w2r, (int)((long)D_ * DFF_ / 4));

    // ---- sublayer 1: pre-norm attention ----
    layernorm_kernel<<<M_, 256>>>(x, a1, g1, n_);

    // fused QKV projection: [4096,1024] @ [1024,3072]
    mma_gemm<0,1><<<dim3(D3_ / 128, M_ / 128), 128>>>(
        n_, wqkvr, bqkv_, nullptr, qkv_, M_, D3_, D_, D_, D3_, D3_);

    // fused attention
    flash_attn_kernel<<<dim3(S_ / 64, B_ * H_), 128>>>(qkv_, mask, ctx_);

    // O projection + residual (exact fp32 out)
    mma_gemm<2,0><<<dim3(D_ / 128, M_ / 128), 128>>>(
        ctx_, wor, bo, x, x1_, M_, D_, D_, D_, D_, D_);

    // ---- sublayer 2: pre-norm FFN ----
    layernorm_kernel<<<M_, 256>>>(x1_, a2, g2, n2_);
    mma_gemm<1,1><<<dim3(DFF_ / 128, M_ / 128), 128>>>(
        n2_, w1r, b1, nullptr, ff1_, M_, DFF_, D_, D_, DFF_, DFF_);
    mma_gemm<2,0><<<dim3(D_ / 128, M_ / 128), 128>>>(
        ff1_, w2r, b2, x1_, out, M_, D_, DFF_, DFF_, D_, D_);
}

// round 14
// speedup vs baseline: 1.0009x; 1.0009x over previous
#include <cuda_runtime.h>
#include <math.h>
#include <stddef.h>
#include <stdint.h>

// Problem constants
#define B_    2
#define S_    2048
#define D_    1024
#define H_    16
#define DK_   64
#define DFF_  4096
#define M_    (B_ * S_)          // 4096 rows
#define EPS_  1e-6f
#define D3_   (3 * D_)           // 3072

// ---------------------------------------------------------------------------
// Scratch (device globals: allocation-free workaround per harness rules)
// ---------------------------------------------------------------------------
__device__ float g_n   [(size_t)M_ * D_];
__device__ float g_qkv [(size_t)M_ * D3_];     // q|k|v interleaved per row
__device__ float g_ctx [(size_t)M_ * D_];
__device__ float g_x1  [(size_t)M_ * D_];
__device__ float g_n2  [(size_t)M_ * D_];
__device__ float g_ff1 [(size_t)M_ * DFF_];
// rounded (tf32-exact) weights: wqkv(concat [K,3D]) | wo | w1 | w2
__device__ float g_wr  [(size_t)(D_ * D3_ + D_ * D_ + 2 * D_ * DFF_)];
__device__ float g_bqkv[D3_];

// ---------------------------------------------------------------------------
// helpers
// ---------------------------------------------------------------------------
__device__ __forceinline__ float rnd_tf32(float x) {
    uint32_t u;
    asm("cvt.rna.tf32.f32 %0, %1;" : "=r"(u) : "f"(x));
    return __uint_as_float(u);
}

__device__ __forceinline__ void mma_tf32(float* c, const uint32_t* a, const uint32_t* b) {
    asm volatile(
        "mma.sync.aligned.m16n8k8.row.col.f32.tf32.tf32.f32 "
        "{%0,%1,%2,%3}, {%4,%5,%6,%7}, {%8,%9}, {%0,%1,%2,%3};"
        : "+f"(c[0]), "+f"(c[1]), "+f"(c[2]), "+f"(c[3])
        : "r"(a[0]), "r"(a[1]), "r"(a[2]), "r"(a[3]), "r"(b[0]), "r"(b[1]));
}

__device__ __forceinline__ void cp16(float* s, const float* g) {
    uint32_t sa = (uint32_t)__cvta_generic_to_shared(s);
    asm volatile("cp.async.cg.shared.global [%0], [%1], 16;\n" :: "r"(sa), "l"(g));
}
__device__ __forceinline__ void cp_commit() {
    asm volatile("cp.async.commit_group;\n");
}
template<int N>
__device__ __forceinline__ void cp_wait() {
    asm volatile("cp.async.wait_group %0;\n" :: "n"(N));
}

// ---------------------------------------------------------------------------
// Weight pre-round kernels
// ---------------------------------------------------------------------------
__global__ void roundw_kernel(const float* __restrict__ in, float* __restrict__ out,
                              int n4) {
    int i = blockIdx.x * blockDim.x + threadIdx.x;
    int stride = gridDim.x * blockDim.x;
    for (; i < n4; i += stride) {
        float4 v = ((const float4*)in)[i];
        v.x = rnd_tf32(v.x); v.y = rnd_tf32(v.y);
        v.z = rnd_tf32(v.z); v.w = rnd_tf32(v.w);
        ((float4*)out)[i] = v;
    }
}

// wqkv[k][n] (n<1024: wq, <2048: wk, else wv), rounded; also bias concat.
__global__ void round_qkv_kernel(const float* __restrict__ wq,
                                 const float* __restrict__ wk,
                                 const float* __restrict__ wv,
                                 const float* __restrict__ bq,
                                 const float* __restrict__ bk,
                                 const float* __restrict__ bv,
                                 float* __restrict__ wout,
                                 float* __restrict__ bout) {
    const int CH = D3_ / 4;                 // 768 float4 per row
    int i = blockIdx.x * blockDim.x + threadIdx.x;
    int stride = gridDim.x * blockDim.x;
    for (; i < D_ * CH; i += stride) {
        int k = i / CH, c4 = i % CH;
        int n = c4 * 4;
        const float* src = (n < D_)     ? (wq + (size_t)k * D_ + n)
                         : (n < 2 * D_) ? (wk + (size_t)k * D_ + n - D_)
                                        : (wv + (size_t)k * D_ + n - 2 * D_);
        float4 v = *(const float4*)src;
        v.x = rnd_tf32(v.x); v.y = rnd_tf32(v.y);
        v.z = rnd_tf32(v.z); v.w = rnd_tf32(v.w);
        ((float4*)wout)[i] = v;
    }
    int t = blockIdx.x * blockDim.x + threadIdx.x;
    if (t < D3_) {
        bout[t] = (t < D_) ? bq[t] : (t < 2 * D_) ? bk[t - D_] : bv[t - 2 * D_];
    }
}

// ---------------------------------------------------------------------------
// tf32 tensor-core GEMM: 3-stage cp.async pipeline, BK=16, XOR-swizzled
// pad-free smem (exactly 48KB static), ONE __syncthreads per k-tile.
// __launch_bounds__(128, 2): 256 regs/thread — acc[4][8][4] (128 regs) must
// NOT spill (the (128,4) variant capped regs at 128 and spilled: 2.4x slower).
// 128 threads = 4 warps (2x2), WM=64, WN=64.
// ---------------------------------------------------------------------------
template<int EPI, int RND>
__global__ void __launch_bounds__(128, 2)
mma_gemm(const float* __restrict__ Ag, const float* __restrict__ Bg,
         const float* __restrict__ bias, const float* __restrict__ Res,
         float* __restrict__ Cg,
         int M, int N, int K, int lda, int ldb, int ldc) {
    constexpr int BM = 128, BN = 128, BK = 16;
    constexpr int MA = 4, NA = 8;
    constexpr int ASZ = BM * BK;
    constexpr int BSZ = BK * BN;

    __shared__ float As[3][ASZ];
    __shared__ float Bs[3][BSZ];

    int tid = threadIdx.x;
    int lane = tid & 31, wid = tid >> 5;
    int wm = wid >> 1, wn = wid & 1;
    int gid = lane >> 2, tg = lane & 3;
    int bx = blockIdx.x, by = blockIdx.y;

    const float* A = Ag + (size_t)(by * BM) * lda;
    const float* Bp = Bg;

    float acc[MA][NA][4] = {};

    const int swa = 4 * (gid >> 1);
    const int swb = 8 * tg;

    auto load_stage = [&](int kt, int st) {
        float* as = As[st];
        float* bs = Bs[st];
        int k0 = kt * BK;
        #pragma unroll
        for (int i = tid; i < BM * BK / 4; i += 128) {
            int r = i >> 2, q = (i & 3) << 2;
            cp16(as + r * 16 + (q ^ (4 * ((r >> 1) & 3))),
                 A + (size_t)r * lda + k0 + q);
        }
        #pragma unroll
        for (int i = tid; i < BK * BN / 4; i += 128) {
            int kr = i >> 5, q = (i & 31) << 2;
            cp16(bs + kr * 128 + (q ^ (8 * (kr & 3))),
                 Bp + (size_t)(k0 + kr) * ldb + bx * BN + q);
        }
        cp_commit();
    };

    int tiles = K / BK;
    load_stage(0, 0);
    load_stage(1, 1);

    for (int t = 0; t < tiles; t++) {
        if (t + 1 < tiles) cp_wait<1>(); else cp_wait<0>();
        __syncthreads();
        if (t + 2 < tiles) load_stage(t + 2, (t + 2) % 3);

        const float* as = As[t % 3];
        const float* bs = Bs[t % 3];
        #pragma unroll
        for (int ks = 0; ks < BK; ks += 8) {
            uint32_t af[MA][4], bf[NA][2];
            int c0 = (ks + tg) ^ swa;
            int c1 = (ks + tg + 4) ^ swa;
            #pragma unroll
            for (int ma = 0; ma < MA; ma++) {
                int m = wm * 64 + ma * 16 + gid;
                af[ma][0] = __float_as_uint(as[m * 16 + c0]);
                af[ma][1] = __float_as_uint(as[(m + 8) * 16 + c0]);
                af[ma][2] = __float_as_uint(as[m * 16 + c1]);
                af[ma][3] = __float_as_uint(as[(m + 8) * 16 + c1]);
            }
            int rb0 = (ks + tg) * 128, rb1 = (ks + tg + 4) * 128;
            #pragma unroll
            for (int na = 0; na < NA; na++) {
                int n = (wn * 64 + na * 8 + gid) ^ swb;
                bf[na][0] = __float_as_uint(bs[rb0 + n]);
                bf[na][1] = __float_as_uint(bs[rb1 + n]);
            }
            #pragma unroll
            for (int ma = 0; ma < MA; ma++)
                #pragma unroll
                for (int na = 0; na < NA; na++)
                    mma_tf32(acc[ma][na], af[ma], bf[na]);
        }
    }

    #pragma unroll
    for (int ma = 0; ma < MA; ma++) {
        #pragma unroll
        for (int na = 0; na < NA; na++) {
            int r = by * BM + wm * 64 + ma * 16 + gid;
            int c = bx * BN + wn * 64 + na * 8 + tg * 2;
            float o0 = acc[ma][na][0], o1 = acc[ma][na][1];
            float o2 = acc[ma][na][2], o3 = acc[ma][na][3];
            {
                float b0 = bias[c], b1 = bias[c + 1];
                o0 += b0; o1 += b1; o2 += b0; o3 += b1;
            }
            if (EPI == 1) {
                o0 = fmaxf(o0, 0.f); o1 = fmaxf(o1, 0.f);
                o2 = fmaxf(o2, 0.f); o3 = fmaxf(o3, 0.f);
            }
            if (EPI == 2) {
                const float* rp0 = Res + (size_t)r * ldc + c;
                const float* rp1 = Res + (size_t)(r + 8) * ldc + c;
                o0 += rp0[0]; o1 += rp0[1];
                o2 += rp1[0]; o3 += rp1[1];
            }
            if (RND) {
                o0 = rnd_tf32(o0); o1 = rnd_tf32(o1);
                o2 = rnd_tf32(o2); o3 = rnd_tf32(o3);
            }
            float2 p0 = {o0, o1}, p1 = {o2, o3};
            *(float2*)(Cg + (size_t)r * ldc + c) = p0;
            *(float2*)(Cg + (size_t)(r + 8) * ldc + c) = p1;
        }
    }
}

// ---------------------------------------------------------------------------
// Flash attention over interleaved qkv buffer (row stride 3D).
// THIS ROUND: occupancy 2 -> 3 CTAs/SM (the only change vs the 1005.6us
// kernel). ~150 live regs fits the 170-reg cap at 384 thr/SM; +50% warps
// to hide the serial load->S->softmax->PV latency chain.
// ---------------------------------------------------------------------------
__global__ void __launch_bounds__(128, 3)
flash_attn_kernel(const float* __restrict__ qkvg, const int* __restrict__ maskg,
                  float* __restrict__ ctxg) {
    __shared__ float sKP[64 * 68];
    __shared__ float sV [64 * 72];
    __shared__ int   sMask[S_];
    __shared__ float sRedM[2][64];
    __shared__ float sRedS[2][64];

    int tid = threadIdx.x;
    int lane = tid & 31, wid = tid >> 5;
    int wm = wid >> 1, wn = wid & 1;
    int gid = lane >> 2, tg = lane & 3;
    int qt = blockIdx.x, z = blockIdx.y;
    int bb = z >> 4, hh = z & 15;

    const size_t SD3 = (size_t)S_ * D3_;
    const float* qp = qkvg + bb * SD3 + hh * DK_ + (size_t)(qt * 64) * D3_;
    const float* kp = qkvg + bb * SD3 + D_ + hh * DK_;
    const float* vp = qkvg + bb * SD3 + 2 * D_ + hh * DK_;

    #pragma unroll
    for (int i = tid; i < S_ / 4; i += 128)
        ((int4*)sMask)[i] = ((const int4*)(maskg + bb * S_))[i];

    uint32_t qf[2][8][4];
    #pragma unroll
    for (int ma = 0; ma < 2; ma++) {
        int r0 = wm * 32 + ma * 16 + gid;
        #pragma unroll
        for (int ks = 0; ks < 8; ks++) {
            int c0 = ks * 8 + tg;
            qf[ma][ks][0] = __float_as_uint(qp[(size_t)r0 * D3_ + c0]);
            qf[ma][ks][1] = __float_as_uint(qp[(size_t)(r0 + 8) * D3_ + c0]);
            qf[ma][ks][2] = __float_as_uint(qp[(size_t)r0 * D3_ + c0 + 4]);
            qf[ma][ks][3] = __float_as_uint(qp[(size_t)(r0 + 8) * D3_ + c0 + 4]);
        }
    }

    float oacc[2][4][4] = {};
    float m_run[2][2], l_run[2][2];
    #pragma unroll
    for (int ma = 0; ma < 2; ma++)
        #pragma unroll
        for (int h = 0; h < 2; h++) { m_run[ma][h] = -INFINITY; l_run[ma][h] = 0.f; }

    for (int kt = 0; kt < S_ / 64; kt++) {
        int k0 = kt * 64;
        #pragma unroll
        for (int i = tid; i < 1024; i += 128) {
            int n = i >> 4, q4 = (i & 15) << 2;
            cp16(&sKP[n * 68 + q4], kp + (size_t)(k0 + n) * D3_ + q4);
        }
        cp_commit();
        #pragma unroll
        for (int i = tid; i < 1024; i += 128) {
            int n = i >> 4, q4 = (i & 15) << 2;
            cp16(&sV[n * 72 + q4], vp + (size_t)(k0 + n) * D3_ + q4);
        }
        cp_commit();
        cp_wait<1>();
        __syncthreads();

        float sacc[2][4][4] = {};
        #pragma unroll
        for (int ks = 0; ks < 8; ks++) {
            uint32_t kf[4][2];
            #pragma unroll
            for (int na = 0; na < 4; na++) {
                int n = wn * 32 + na * 8 + gid;
                kf[na][0] = __float_as_uint(sKP[n * 68 + ks * 8 + tg]);
                kf[na][1] = __float_as_uint(sKP[n * 68 + ks * 8 + tg + 4]);
            }
            #pragma unroll
            for (int ma = 0; ma < 2; ma++)
                #pragma unroll
                for (int na = 0; na < 4; na++)
                    mma_tf32(sacc[ma][na], qf[ma][ks], kf[na]);
        }

        float tmax[2][2] = {{-INFINITY, -INFINITY}, {-INFINITY, -INFINITY}};
        #pragma unroll
        for (int ma = 0; ma < 2; ma++)
            #pragma unroll
            for (int na = 0; na < 4; na++) {
                int cb = wn * 32 + na * 8 + 2 * tg;
                int mk0 = sMask[k0 + cb], mk1 = sMask[k0 + cb + 1];
                float s0 = mk0 ? sacc[ma][na][0] * 0.125f : -1e9f;
                float s1 = mk1 ? sacc[ma][na][1] * 0.125f : -1e9f;
                float s2 = mk0 ? sacc[ma][na][2] * 0.125f : -1e9f;
                float s3 = mk1 ? sacc[ma][na][3] * 0.125f : -1e9f;
                sacc[ma][na][0] = s0; sacc[ma][na][1] = s1;
                sacc[ma][na][2] = s2; sacc[ma][na][3] = s3;
                tmax[ma][0] = fmaxf(tmax[ma][0], fmaxf(s0, s1));
                tmax[ma][1] = fmaxf(tmax[ma][1], fmaxf(s2, s3));
            }
        #pragma unroll
        for (int ma = 0; ma < 2; ma++)
            #pragma unroll
            for (int h = 0; h < 2; h++) {
                float v = tmax[ma][h];
                v = fmaxf(v, __shfl_xor_sync(0xffffffffu, v, 1));
                v = fmaxf(v, __shfl_xor_sync(0xffffffffu, v, 2));
                tmax[ma][h] = v;
            }
        if (tg == 0) {
            #pragma unroll
            for (int ma = 0; ma < 2; ma++) {
                sRedM[wn][wm * 32 + ma * 16 + gid]     = tmax[ma][0];
                sRedM[wn][wm * 32 + ma * 16 + gid + 8] = tmax[ma][1];
            }
        }
        __syncthreads();

        float mnew[2][2], fsc[2][2], psum[2][2];
        #pragma unroll
        for (int ma = 0; ma < 2; ma++)
            #pragma unroll
            for (int h = 0; h < 2; h++) {
                int row = wm * 32 + ma * 16 + gid + h * 8;
                float mt = fmaxf(sRedM[0][row], sRedM[1][row]);
                float mn = fmaxf(m_run[ma][h], mt);
                mnew[ma][h] = mn;
                fsc[ma][h] = __expf(m_run[ma][h] - mn);
                psum[ma][h] = 0.f;
            }
        #pragma unroll
        for (int ma = 0; ma < 2; ma++) {
            int r0 = wm * 32 + ma * 16 + gid;
            #pragma unroll
            for (int na = 0; na < 4; na++) {
                int cb = wn * 32 + na * 8 + 2 * tg;
                float p0 = __expf(sacc[ma][na][0] - mnew[ma][0]);
                float p1 = __expf(sacc[ma][na][1] - mnew[ma][0]);
                float p2 = __expf(sacc[ma][na][2] - mnew[ma][1]);
                float p3 = __expf(sacc[ma][na][3] - mnew[ma][1]);
                psum[ma][0] += p0 + p1;
                psum[ma][1] += p2 + p3;
                sKP[r0 * 68 + cb]           = rnd_tf32(p0);
                sKP[r0 * 68 + cb + 1]       = rnd_tf32(p1);
                sKP[(r0 + 8) * 68 + cb]     = rnd_tf32(p2);
                sKP[(r0 + 8) * 68 + cb + 1] = rnd_tf32(p3);
            }
        }
        #pragma unroll
        for (int ma = 0; ma < 2; ma++)
            #pragma unroll
            for (int h = 0; h < 2; h++) {
                float v = psum[ma][h];
                v += __shfl_xor_sync(0xffffffffu, v, 1);
                v += __shfl_xor_sync(0xffffffffu, v, 2);
                psum[ma][h] = v;
            }
        if (tg == 0) {
            #pragma unroll
            for (int ma = 0; ma < 2; ma++) {
                sRedS[wn][wm * 32 + ma * 16 + gid]     = psum[ma][0];
                sRedS[wn][wm * 32 + ma * 16 + gid + 8] = psum[ma][1];
            }
        }
        cp_wait<0>();
        __syncthreads();

        #pragma unroll
        for (int ma = 0; ma < 2; ma++)
            #pragma unroll
            for (int h = 0; h < 2; h++) {
                int row = wm * 32 + ma * 16 + gid + h * 8;
                l_run[ma][h] = l_run[ma][h] * fsc[ma][h]
                             + (sRedS[0][row] + sRedS[1][row]);
                m_run[ma][h] = mnew[ma][h];
            }
        #pragma unroll
        for (int ma = 0; ma < 2; ma++)
            #pragma unroll
            for (int na = 0; na < 4; na++) {
                oacc[ma][na][0] *= fsc[ma][0];
                oacc[ma][na][1] *= fsc[ma][0];
                oacc[ma][na][2] *= fsc[ma][1];
                oacc[ma][na][3] *= fsc[ma][1];
            }

        #pragma unroll
        for (int ks = 0; ks < 8; ks++) {
            uint32_t af[2][4], vf[4][2];
            #pragma unroll
            for (int ma = 0; ma < 2; ma++) {
                int m0 = wm * 32 + ma * 16 + gid;
                af[ma][0] = __float_as_uint(sKP[m0 * 68 + ks * 8 + tg]);
                af[ma][1] = __float_as_uint(sKP[(m0 + 8) * 68 + ks * 8 + tg]);
                af[ma][2] = __float_as_uint(sKP[m0 * 68 + ks * 8 + tg + 4]);
                af[ma][3] = __float_as_uint(sKP[(m0 + 8) * 68 + ks * 8 + tg + 4]);
            }
            #pragma unroll
            for (int na = 0; na < 4; na++) {
                int n = wn * 32 + na * 8 + gid;
                vf[na][0] = __float_as_uint(sV[(ks * 8 + tg) * 72 + n]);
                vf[na][1] = __float_as_uint(sV[(ks * 8 + tg + 4) * 72 + n]);
            }
            #pragma unroll
            for (int ma = 0; ma < 2; ma++)
                #pragma unroll
                for (int na = 0; na < 4; na++)
                    mma_tf32(oacc[ma][na], af[ma], vf[na]);
        }
        __syncthreads();
    }

    float* cp_ = ctxg + bb * (size_t)S_ * D_ + hh * DK_;
    #pragma unroll
    for (int ma = 0; ma < 2; ma++) {
        int r0 = qt * 64 + wm * 32 + ma * 16 + gid;
        float inv0 = 1.0f / l_run[ma][0];
        float inv1 = 1.0f / l_run[ma][1];
        #pragma unroll
        for (int na = 0; na < 4; na++) {
            int c = wn * 32 + na * 8 + 2 * tg;
            float2 p0 = {rnd_tf32(oacc[ma][na][0] * inv0),
                         rnd_tf32(oacc[ma][na][1] * inv0)};
            float2 p1 = {rnd_tf32(oacc[ma][na][2] * inv1),
                         rnd_tf32(oacc[ma][na][3] * inv1)};
            *(float2*)(cp_ + (size_t)r0 * D_ + c) = p0;
            *(float2*)(cp_ + (size_t)(r0 + 8) * D_ + c) = p1;
        }
    }
}

// ---------------------------------------------------------------------------
// Block-wide allreduce (256 threads = 8 warps)
// ---------------------------------------------------------------------------
__device__ __forceinline__ float allreduce_sum(float v, float* sh) {
    #pragma unroll
    for (int o = 16; o > 0; o >>= 1) v += __shfl_xor_sync(0xffffffffu, v, o);
    int lane = threadIdx.x & 31, wid = threadIdx.x >> 5;
    if (lane == 0) sh[wid] = v;
    __syncthreads();
    if (wid == 0) {
        float r = sh[lane & 7];
        #pragma unroll
        for (int o = 4; o > 0; o >>= 1) r += __shfl_xor_sync(0xffffffffu, r, o);
        if (lane == 0) sh[0] = r;
    }
    __syncthreads();
    float r = sh[0];
    __syncthreads();
    return r;
}

// ---------------------------------------------------------------------------
// LayerNorm: one block (256 thr) per row of D=1024. ddof=1, eps on std.
// ---------------------------------------------------------------------------
__global__ void layernorm_kernel(const float* __restrict__ x,
                                 const float* __restrict__ alpha,
                                 const float* __restrict__ beta,
                                 float* __restrict__ out) {
    __shared__ float sh[32];
    size_t row = blockIdx.x;
    const float4 v = ((const float4*)(x + row * D_))[threadIdx.x];
    float s = v.x + v.y + v.z + v.w;
    s = allreduce_sum(s, sh);
    float mean = s * (1.0f / D_);
    float dx = v.x - mean, dy = v.y - mean, dz = v.z - mean, dw = v.w - mean;
    float var = dx * dx + dy * dy + dz * dz + dw * dw;
    var = allreduce_sum(var, sh) * (1.0f / (D_ - 1));
    float scale = alpha[0] / (sqrtf(var) + EPS_);
    float bias = beta[0];
    float4 o;
    o.x = rnd_tf32(dx * scale + bias);
    o.y = rnd_tf32(dy * scale + bias);
    o.z = rnd_tf32(dz * scale + bias);
    o.w = rnd_tf32(dw * scale + bias);
    ((float4*)(out + row * D_))[threadIdx.x] = o;
}

// ---------------------------------------------------------------------------
// Launch — no attribute calls, all static smem, capture-safe.
// ---------------------------------------------------------------------------
extern "C" void kernel_launch(void* const* d_in, const int* in_sizes, int n_in,
                              void* d_out, int out_size) {
    const float* x    = (const float*)d_in[0];
    const int*   mask = (const int*)  d_in[1];
    const float* wq   = (const float*)d_in[2];
    const float* bq   = (const float*)d_in[3];
    const float* wk   = (const float*)d_in[4];
    const float* bk   = (const float*)d_in[5];
    const float* wv   = (const float*)d_in[6];
    const float* bv   = (const float*)d_in[7];
    const float* wo   = (const float*)d_in[8];
    const float* bo   = (const float*)d_in[9];
    const float* w1   = (const float*)d_in[10];
    const float* b1   = (const float*)d_in[11];
    const float* w2   = (const float*)d_in[12];
    const float* b2   = (const float*)d_in[13];
    const float* a1   = (const float*)d_in[14];
    const float* g1   = (const float*)d_in[15];
    const float* a2   = (const float*)d_in[16];
    const float* g2   = (const float*)d_in[17];
    float* out = (float*)d_out;

    float *n_, *qkv_, *ctx_, *x1_, *n2_, *ff1_, *wr_, *bqkv_;
    cudaGetSymbolAddress((void**)&n_,    g_n);
    cudaGetSymbolAddress((void**)&qkv_,  g_qkv);
    cudaGetSymbolAddress((void**)&ctx_,  g_ctx);
    cudaGetSymbolAddress((void**)&x1_,   g_x1);
    cudaGetSymbolAddress((void**)&n2_,   g_n2);
    cudaGetSymbolAddress((void**)&ff1_,  g_ff1);
    cudaGetSymbolAddress((void**)&wr_,   g_wr);
    cudaGetSymbolAddress((void**)&bqkv_, g_bqkv);

    const long DD = (long)D_ * D_;
    float* wqkvr = wr_;                              // [K=1024, 3072]
    float* wor   = wr_ + (long)D_ * D3_;
    float* w1r   = wor + DD;
    float* w2r   = w1r + (long)D_ * DFF_;

    round_qkv_kernel<<<512, 256>>>(wq, wk, wv, bq, bk, bv, wqkvr, bqkv_);
    roundw_kernel<<<512, 256>>>(wo, wor, (int)(DD / 4));
    roundw_kernel<<<512, 256>>>(w1, w1r, (int)((long)D_ * DFF_ / 4));
    roundw_kernel<<<512, 256>>>(w2, w2r, (int)((long)D_ * DFF_ / 4));

    layernorm_kernel<<<M_, 256>>>(x, a1, g1, n_);

    mma_gemm<0,1><<<dim3(D3_ / 128, M_ / 128), 128>>>(
        n_, wqkvr, bqkv_, nullptr, qkv_, M_, D3_, D_, D_, D3_, D3_);

    flash_attn_kernel<<<dim3(S_ / 64, B_ * H_), 128>>>(qkv_, mask, ctx_);

    mma_gemm<2,0><<<dim3(D_ / 128, M_ / 128), 128>>>(
        ctx_, wor, bo, x, x1_, M_, D_, D_, D_, D_, D_);

    layernorm_kernel<<<M_, 256>>>(x1_, a2, g2, n2_);
    mma_gemm<1,1><<<dim3(DFF_ / 128, M_ / 128), 128>>>(
        n2_, w1r, b1, nullptr, ff1_, M_, DFF_, D_, D_, DFF_, DFF_);
    mma_gemm<2,0><<<dim3(D_ / 128, M_ / 128), 128>>>(
        ff1_, w2r, b2, x1_, out, M_, D_, DFF_, DFF_, D_, D_);
}

// round 16
// speedup vs baseline: 1.0017x; 1.0008x over previous
#include <cuda_runtime.h>
#include <math.h>
#include <stddef.h>
#include <stdint.h>

// Problem constants
#define B_    2
#define S_    2048
#define D_    1024
#define H_    16
#define DK_   64
#define DFF_  4096
#define M_    (B_ * S_)          // 4096 rows
#define EPS_  1e-6f
#define D3_   (3 * D_)           // 3072

// ---------------------------------------------------------------------------
// Scratch (device globals: allocation-free workaround per harness rules)
// ---------------------------------------------------------------------------
__device__ float g_n   [(size_t)M_ * D_];
__device__ float g_qkv [(size_t)M_ * D3_];     // q|k|v interleaved per row
__device__ float g_ctx [(size_t)M_ * D_];
__device__ float g_x1  [(size_t)M_ * D_];
__device__ float g_n2  [(size_t)M_ * D_];
__device__ float g_ff1 [(size_t)M_ * DFF_];
// rounded (tf32-exact) weights: wqkv(concat [K,3D]) | wo | w1 | w2
__device__ float g_wr  [(size_t)(D_ * D3_ + D_ * D_ + 2 * D_ * DFF_)];
__device__ float g_bqkv[D3_];

// ---------------------------------------------------------------------------
// helpers
// ---------------------------------------------------------------------------
__device__ __forceinline__ float rnd_tf32(float x) {
    uint32_t u;
    asm("cvt.rna.tf32.f32 %0, %1;" : "=r"(u) : "f"(x));
    return __uint_as_float(u);
}

__device__ __forceinline__ void mma_tf32(float* c, const uint32_t* a, const uint32_t* b) {
    asm volatile(
        "mma.sync.aligned.m16n8k8.row.col.f32.tf32.tf32.f32 "
        "{%0,%1,%2,%3}, {%4,%5,%6,%7}, {%8,%9}, {%0,%1,%2,%3};"
        : "+f"(c[0]), "+f"(c[1]), "+f"(c[2]), "+f"(c[3])
        : "r"(a[0]), "r"(a[1]), "r"(a[2]), "r"(a[3]), "r"(b[0]), "r"(b[1]));
}

__device__ __forceinline__ void cp16(float* s, const float* g) {
    uint32_t sa = (uint32_t)__cvta_generic_to_shared(s);
    asm volatile("cp.async.cg.shared.global [%0], [%1], 16;\n" :: "r"(sa), "l"(g));
}
__device__ __forceinline__ void cp_commit() {
    asm volatile("cp.async.commit_group;\n");
}
template<int N>
__device__ __forceinline__ void cp_wait() {
    asm volatile("cp.async.wait_group %0;\n" :: "n"(N));
}

// ---------------------------------------------------------------------------
// Weight pre-round kernels
// ---------------------------------------------------------------------------
__global__ void roundw_kernel(const float* __restrict__ in, float* __restrict__ out,
                              int n4) {
    int i = blockIdx.x * blockDim.x + threadIdx.x;
    int stride = gridDim.x * blockDim.x;
    for (; i < n4; i += stride) {
        float4 v = ((const float4*)in)[i];
        v.x = rnd_tf32(v.x); v.y = rnd_tf32(v.y);
        v.z = rnd_tf32(v.z); v.w = rnd_tf32(v.w);
        ((float4*)out)[i] = v;
    }
}

// wqkv[k][n] (n<1024: wq, <2048: wk, else wv), rounded; also bias concat.
__global__ void round_qkv_kernel(const float* __restrict__ wq,
                                 const float* __restrict__ wk,
                                 const float* __restrict__ wv,
                                 const float* __restrict__ bq,
                                 const float* __restrict__ bk,
                                 const float* __restrict__ bv,
                                 float* __restrict__ wout,
                                 float* __restrict__ bout) {
    const int CH = D3_ / 4;                 // 768 float4 per row
    int i = blockIdx.x * blockDim.x + threadIdx.x;
    int stride = gridDim.x * blockDim.x;
    for (; i < D_ * CH; i += stride) {
        int k = i / CH, c4 = i % CH;
        int n = c4 * 4;
        const float* src = (n < D_)     ? (wq + (size_t)k * D_ + n)
                         : (n < 2 * D_) ? (wk + (size_t)k * D_ + n - D_)
                                        : (wv + (size_t)k * D_ + n - 2 * D_);
        float4 v = *(const float4*)src;
        v.x = rnd_tf32(v.x); v.y = rnd_tf32(v.y);
        v.z = rnd_tf32(v.z); v.w = rnd_tf32(v.w);
        ((float4*)wout)[i] = v;
    }
    int t = blockIdx.x * blockDim.x + threadIdx.x;
    if (t < D3_) {
        bout[t] = (t < D_) ? bq[t] : (t < 2 * D_) ? bk[t - D_] : bv[t - 2 * D_];
    }
}

// ---------------------------------------------------------------------------
// tf32 tensor-core GEMM: 3-stage cp.async pipeline, BK=16, XOR-swizzled
// pad-free smem (exactly 48KB static), ONE __syncthreads per k-tile.
// __launch_bounds__(128, 2): 256 regs/thread — acc[4][8][4] (128 regs) must
// NOT spill (the (128,4) variant capped regs at 128 and spilled: 2.4x slower).
// 128 threads = 4 warps (2x2), WM=64, WN=64.
// ---------------------------------------------------------------------------
template<int EPI, int RND>
__global__ void __launch_bounds__(128, 2)
mma_gemm(const float* __restrict__ Ag, const float* __restrict__ Bg,
         const float* __restrict__ bias, const float* __restrict__ Res,
         float* __restrict__ Cg,
         int M, int N, int K, int lda, int ldb, int ldc) {
    constexpr int BM = 128, BN = 128, BK = 16;
    constexpr int MA = 4, NA = 8;
    constexpr int ASZ = BM * BK;
    constexpr int BSZ = BK * BN;

    __shared__ float As[3][ASZ];
    __shared__ float Bs[3][BSZ];

    int tid = threadIdx.x;
    int lane = tid & 31, wid = tid >> 5;
    int wm = wid >> 1, wn = wid & 1;
    int gid = lane >> 2, tg = lane & 3;
    int bx = blockIdx.x, by = blockIdx.y;

    const float* A = Ag + (size_t)(by * BM) * lda;
    const float* Bp = Bg;

    float acc[MA][NA][4] = {};

    const int swa = 4 * (gid >> 1);
    const int swb = 8 * tg;

    auto load_stage = [&](int kt, int st) {
        float* as = As[st];
        float* bs = Bs[st];
        int k0 = kt * BK;
        #pragma unroll
        for (int i = tid; i < BM * BK / 4; i += 128) {
            int r = i >> 2, q = (i & 3) << 2;
            cp16(as + r * 16 + (q ^ (4 * ((r >> 1) & 3))),
                 A + (size_t)r * lda + k0 + q);
        }
        #pragma unroll
        for (int i = tid; i < BK * BN / 4; i += 128) {
            int kr = i >> 5, q = (i & 31) << 2;
            cp16(bs + kr * 128 + (q ^ (8 * (kr & 3))),
                 Bp + (size_t)(k0 + kr) * ldb + bx * BN + q);
        }
        cp_commit();
    };

    int tiles = K / BK;
    load_stage(0, 0);
    load_stage(1, 1);

    for (int t = 0; t < tiles; t++) {
        if (t + 1 < tiles) cp_wait<1>(); else cp_wait<0>();
        __syncthreads();
        if (t + 2 < tiles) load_stage(t + 2, (t + 2) % 3);

        const float* as = As[t % 3];
        const float* bs = Bs[t % 3];
        #pragma unroll
        for (int ks = 0; ks < BK; ks += 8) {
            uint32_t af[MA][4], bf[NA][2];
            int c0 = (ks + tg) ^ swa;
            int c1 = (ks + tg + 4) ^ swa;
            #pragma unroll
            for (int ma = 0; ma < MA; ma++) {
                int m = wm * 64 + ma * 16 + gid;
                af[ma][0] = __float_as_uint(as[m * 16 + c0]);
                af[ma][1] = __float_as_uint(as[(m + 8) * 16 + c0]);
                af[ma][2] = __float_as_uint(as[m * 16 + c1]);
                af[ma][3] = __float_as_uint(as[(m + 8) * 16 + c1]);
            }
            int rb0 = (ks + tg) * 128, rb1 = (ks + tg + 4) * 128;
            #pragma unroll
            for (int na = 0; na < NA; na++) {
                int n = (wn * 64 + na * 8 + gid) ^ swb;
                bf[na][0] = __float_as_uint(bs[rb0 + n]);
                bf[na][1] = __float_as_uint(bs[rb1 + n]);
            }
            #pragma unroll
            for (int ma = 0; ma < MA; ma++)
                #pragma unroll
                for (int na = 0; na < NA; na++)
                    mma_tf32(acc[ma][na], af[ma], bf[na]);
        }
    }

    #pragma unroll
    for (int ma = 0; ma < MA; ma++) {
        #pragma unroll
        for (int na = 0; na < NA; na++) {
            int r = by * BM + wm * 64 + ma * 16 + gid;
            int c = bx * BN + wn * 64 + na * 8 + tg * 2;
            float o0 = acc[ma][na][0], o1 = acc[ma][na][1];
            float o2 = acc[ma][na][2], o3 = acc[ma][na][3];
            {
                float b0 = bias[c], b1 = bias[c + 1];
                o0 += b0; o1 += b1; o2 += b0; o3 += b1;
            }
            if (EPI == 1) {
                o0 = fmaxf(o0, 0.f); o1 = fmaxf(o1, 0.f);
                o2 = fmaxf(o2, 0.f); o3 = fmaxf(o3, 0.f);
            }
            if (EPI == 2) {
                const float* rp0 = Res + (size_t)r * ldc + c;
                const float* rp1 = Res + (size_t)(r + 8) * ldc + c;
                o0 += rp0[0]; o1 += rp0[1];
                o2 += rp1[0]; o3 += rp1[1];
            }
            if (RND) {
                o0 = rnd_tf32(o0); o1 = rnd_tf32(o1);
                o2 = rnd_tf32(o2); o3 = rnd_tf32(o3);
            }
            float2 p0 = {o0, o1}, p1 = {o2, o3};
            *(float2*)(Cg + (size_t)r * ldc + c) = p0;
            *(float2*)(Cg + (size_t)(r + 8) * ldc + c) = p1;
        }
    }
}

// ---------------------------------------------------------------------------
// Flash attention over interleaved qkv buffer (row stride 3D).
// THIS ROUND: occupancy 2 -> 3 CTAs/SM (the only change vs the 1005.6us
// kernel). ~150 live regs fits the 170-reg cap at 384 thr/SM; +50% warps
// to hide the serial load->S->softmax->PV latency chain.
// ---------------------------------------------------------------------------
__global__ void __launch_bounds__(128, 3)
flash_attn_kernel(const float* __restrict__ qkvg, const int* __restrict__ maskg,
                  float* __restrict__ ctxg) {
    __shared__ float sKP[64 * 68];
    __shared__ float sV [64 * 72];
    __shared__ int   sMask[S_];
    __shared__ float sRedM[2][64];
    __shared__ float sRedS[2][64];

    int tid = threadIdx.x;
    int lane = tid & 31, wid = tid >> 5;
    int wm = wid >> 1, wn = wid & 1;
    int gid = lane >> 2, tg = lane & 3;
    int qt = blockIdx.x, z = blockIdx.y;
    int bb = z >> 4, hh = z & 15;

    const size_t SD3 = (size_t)S_ * D3_;
    const float* qp = qkvg + bb * SD3 + hh * DK_ + (size_t)(qt * 64) * D3_;
    const float* kp = qkvg + bb * SD3 + D_ + hh * DK_;
    const float* vp = qkvg + bb * SD3 + 2 * D_ + hh * DK_;

    #pragma unroll
    for (int i = tid; i < S_ / 4; i += 128)
        ((int4*)sMask)[i] = ((const int4*)(maskg + bb * S_))[i];

    uint32_t qf[2][8][4];
    #pragma unroll
    for (int ma = 0; ma < 2; ma++) {
        int r0 = wm * 32 + ma * 16 + gid;
        #pragma unroll
        for (int ks = 0; ks < 8; ks++) {
            int c0 = ks * 8 + tg;
            qf[ma][ks][0] = __float_as_uint(qp[(size_t)r0 * D3_ + c0]);
            qf[ma][ks][1] = __float_as_uint(qp[(size_t)(r0 + 8) * D3_ + c0]);
            qf[ma][ks][2] = __float_as_uint(qp[(size_t)r0 * D3_ + c0 + 4]);
            qf[ma][ks][3] = __float_as_uint(qp[(size_t)(r0 + 8) * D3_ + c0 + 4]);
        }
    }

    float oacc[2][4][4] = {};
    float m_run[2][2], l_run[2][2];
    #pragma unroll
    for (int ma = 0; ma < 2; ma++)
        #pragma unroll
        for (int h = 0; h < 2; h++) { m_run[ma][h] = -INFINITY; l_run[ma][h] = 0.f; }

    for (int kt = 0; kt < S_ / 64; kt++) {
        int k0 = kt * 64;
        #pragma unroll
        for (int i = tid; i < 1024; i += 128) {
            int n = i >> 4, q4 = (i & 15) << 2;
            cp16(&sKP[n * 68 + q4], kp + (size_t)(k0 + n) * D3_ + q4);
        }
        cp_commit();
        #pragma unroll
        for (int i = tid; i < 1024; i += 128) {
            int n = i >> 4, q4 = (i & 15) << 2;
            cp16(&sV[n * 72 + q4], vp + (size_t)(k0 + n) * D3_ + q4);
        }
        cp_commit();
        cp_wait<1>();
        __syncthreads();

        float sacc[2][4][4] = {};
        #pragma unroll
        for (int ks = 0; ks < 8; ks++) {
            uint32_t kf[4][2];
            #pragma unroll
            for (int na = 0; na < 4; na++) {
                int n = wn * 32 + na * 8 + gid;
                kf[na][0] = __float_as_uint(sKP[n * 68 + ks * 8 + tg]);
                kf[na][1] = __float_as_uint(sKP[n * 68 + ks * 8 + tg + 4]);
            }
            #pragma unroll
            for (int ma = 0; ma < 2; ma++)
                #pragma unroll
                for (int na = 0; na < 4; na++)
                    mma_tf32(sacc[ma][na], qf[ma][ks], kf[na]);
        }

        float tmax[2][2] = {{-INFINITY, -INFINITY}, {-INFINITY, -INFINITY}};
        #pragma unroll
        for (int ma = 0; ma < 2; ma++)
            #pragma unroll
            for (int na = 0; na < 4; na++) {
                int cb = wn * 32 + na * 8 + 2 * tg;
                int mk0 = sMask[k0 + cb], mk1 = sMask[k0 + cb + 1];
                float s0 = mk0 ? sacc[ma][na][0] * 0.125f : -1e9f;
                float s1 = mk1 ? sacc[ma][na][1] * 0.125f : -1e9f;
                float s2 = mk0 ? sacc[ma][na][2] * 0.125f : -1e9f;
                float s3 = mk1 ? sacc[ma][na][3] * 0.125f : -1e9f;
                sacc[ma][na][0] = s0; sacc[ma][na][1] = s1;
                sacc[ma][na][2] = s2; sacc[ma][na][3] = s3;
                tmax[ma][0] = fmaxf(tmax[ma][0], fmaxf(s0, s1));
                tmax[ma][1] = fmaxf(tmax[ma][1], fmaxf(s2, s3));
            }
        #pragma unroll
        for (int ma = 0; ma < 2; ma++)
            #pragma unroll
            for (int h = 0; h < 2; h++) {
                float v = tmax[ma][h];
                v = fmaxf(v, __shfl_xor_sync(0xffffffffu, v, 1));
                v = fmaxf(v, __shfl_xor_sync(0xffffffffu, v, 2));
                tmax[ma][h] = v;
            }
        if (tg == 0) {
            #pragma unroll
            for (int ma = 0; ma < 2; ma++) {
                sRedM[wn][wm * 32 + ma * 16 + gid]     = tmax[ma][0];
                sRedM[wn][wm * 32 + ma * 16 + gid + 8] = tmax[ma][1];
            }
        }
        __syncthreads();

        float mnew[2][2], fsc[2][2], psum[2][2];
        #pragma unroll
        for (int ma = 0; ma < 2; ma++)
            #pragma unroll
            for (int h = 0; h < 2; h++) {
                int row = wm * 32 + ma * 16 + gid + h * 8;
                float mt = fmaxf(sRedM[0][row], sRedM[1][row]);
                float mn = fmaxf(m_run[ma][h], mt);
                mnew[ma][h] = mn;
                fsc[ma][h] = __expf(m_run[ma][h] - mn);
                psum[ma][h] = 0.f;
            }
        #pragma unroll
        for (int ma = 0; ma < 2; ma++) {
            int r0 = wm * 32 + ma * 16 + gid;
            #pragma unroll
            for (int na = 0; na < 4; na++) {
                int cb = wn * 32 + na * 8 + 2 * tg;
                float p0 = __expf(sacc[ma][na][0] - mnew[ma][0]);
                float p1 = __expf(sacc[ma][na][1] - mnew[ma][0]);
                float p2 = __expf(sacc[ma][na][2] - mnew[ma][1]);
                float p3 = __expf(sacc[ma][na][3] - mnew[ma][1]);
                psum[ma][0] += p0 + p1;
                psum[ma][1] += p2 + p3;
                sKP[r0 * 68 + cb]           = rnd_tf32(p0);
                sKP[r0 * 68 + cb + 1]       = rnd_tf32(p1);
                sKP[(r0 + 8) * 68 + cb]     = rnd_tf32(p2);
                sKP[(r0 + 8) * 68 + cb + 1] = rnd_tf32(p3);
            }
        }
        #pragma unroll
        for (int ma = 0; ma < 2; ma++)
            #pragma unroll
            for (int h = 0; h < 2; h++) {
                float v = psum[ma][h];
                v += __shfl_xor_sync(0xffffffffu, v, 1);
                v += __shfl_xor_sync(0xffffffffu, v, 2);
                psum[ma][h] = v;
            }
        if (tg == 0) {
            #pragma unroll
            for (int ma = 0; ma < 2; ma++) {
                sRedS[wn][wm * 32 + ma * 16 + gid]     = psum[ma][0];
                sRedS[wn][wm * 32 + ma * 16 + gid + 8] = psum[ma][1];
            }
        }
        cp_wait<0>();
        __syncthreads();

        #pragma unroll
        for (int ma = 0; ma < 2; ma++)
            #pragma unroll
            for (int h = 0; h < 2; h++) {
                int row = wm * 32 + ma * 16 + gid + h * 8;
                l_run[ma][h] = l_run[ma][h] * fsc[ma][h]
                             + (sRedS[0][row] + sRedS[1][row]);
                m_run[ma][h] = mnew[ma][h];
            }
        #pragma unroll
        for (int ma = 0; ma < 2; ma++)
            #pragma unroll
            for (int na = 0; na < 4; na++) {
                oacc[ma][na][0] *= fsc[ma][0];
                oacc[ma][na][1] *= fsc[ma][0];
                oacc[ma][na][2] *= fsc[ma][1];
                oacc[ma][na][3] *= fsc[ma][1];
            }

        #pragma unroll
        for (int ks = 0; ks < 8; ks++) {
            uint32_t af[2][4], vf[4][2];
            #pragma unroll
            for (int ma = 0; ma < 2; ma++) {
                int m0 = wm * 32 + ma * 16 + gid;
                af[ma][0] = __float_as_uint(sKP[m0 * 68 + ks * 8 + tg]);
                af[ma][1] = __float_as_uint(sKP[(m0 + 8) * 68 + ks * 8 + tg]);
                af[ma][2] = __float_as_uint(sKP[m0 * 68 + ks * 8 + tg + 4]);
                af[ma][3] = __float_as_uint(sKP[(m0 + 8) * 68 + ks * 8 + tg + 4]);
            }
            #pragma unroll
            for (int na = 0; na < 4; na++) {
                int n = wn * 32 + na * 8 + gid;
                vf[na][0] = __float_as_uint(sV[(ks * 8 + tg) * 72 + n]);
                vf[na][1] = __float_as_uint(sV[(ks * 8 + tg + 4) * 72 + n]);
            }
            #pragma unroll
            for (int ma = 0; ma < 2; ma++)
                #pragma unroll
                for (int na = 0; na < 4; na++)
                    mma_tf32(oacc[ma][na], af[ma], vf[na]);
        }
        __syncthreads();
    }

    float* cp_ = ctxg + bb * (size_t)S_ * D_ + hh * DK_;
    #pragma unroll
    for (int ma = 0; ma < 2; ma++) {
        int r0 = qt * 64 + wm * 32 + ma * 16 + gid;
        float inv0 = 1.0f / l_run[ma][0];
        float inv1 = 1.0f / l_run[ma][1];
        #pragma unroll
        for (int na = 0; na < 4; na++) {
            int c = wn * 32 + na * 8 + 2 * tg;
            float2 p0 = {rnd_tf32(oacc[ma][na][0] * inv0),
                         rnd_tf32(oacc[ma][na][1] * inv0)};
            float2 p1 = {rnd_tf32(oacc[ma][na][2] * inv1),
                         rnd_tf32(oacc[ma][na][3] * inv1)};
            *(float2*)(cp_ + (size_t)r0 * D_ + c) = p0;
            *(float2*)(cp_ + (size_t)(r0 + 8) * D_ + c) = p1;
        }
    }
}

// ---------------------------------------------------------------------------
// Block-wide allreduce (256 threads = 8 warps)
// ---------------------------------------------------------------------------
__device__ __forceinline__ float allreduce_sum(float v, float* sh) {
    #pragma unroll
    for (int o = 16; o > 0; o >>= 1) v += __shfl_xor_sync(0xffffffffu, v, o);
    int lane = threadIdx.x & 31, wid = threadIdx.x >> 5;
    if (lane == 0) sh[wid] = v;
    __syncthreads();
    if (wid == 0) {
        float r = sh[lane & 7];
        #pragma unroll
        for (int o = 4; o > 0; o >>= 1) r += __shfl_xor_sync(0xffffffffu, r, o);
        if (lane == 0) sh[0] = r;
    }
    __syncthreads();
    float r = sh[0];
    __syncthreads();
    return r;
}

// ---------------------------------------------------------------------------
// LayerNorm: one block (256 thr) per row of D=1024. ddof=1, eps on std.
// ---------------------------------------------------------------------------
__global__ void layernorm_kernel(const float* __restrict__ x,
                                 const float* __restrict__ alpha,
                                 const float* __restrict__ beta,
                                 float* __restrict__ out) {
    __shared__ float sh[32];
    size_t row = blockIdx.x;
    const float4 v = ((const float4*)(x + row * D_))[threadIdx.x];
    float s = v.x + v.y + v.z + v.w;
    s = allreduce_sum(s, sh);
    float mean = s * (1.0f / D_);
    float dx = v.x - mean, dy = v.y - mean, dz = v.z - mean, dw = v.w - mean;
    float var = dx * dx + dy * dy + dz * dz + dw * dw;
    var = allreduce_sum(var, sh) * (1.0f / (D_ - 1));
    float scale = alpha[0] / (sqrtf(var) + EPS_);
    float bias = beta[0];
    float4 o;
    o.x = rnd_tf32(dx * scale + bias);
    o.y = rnd_tf32(dy * scale + bias);
    o.z = rnd_tf32(dz * scale + bias);
    o.w = rnd_tf32(dw * scale + bias);
    ((float4*)(out + row * D_))[threadIdx.x] = o;
}

// ---------------------------------------------------------------------------
// Launch — no attribute calls, all static smem, capture-safe.
// ---------------------------------------------------------------------------
extern "C" void kernel_launch(void* const* d_in, const int* in_sizes, int n_in,
                              void* d_out, int out_size) {
    const float* x    = (const float*)d_in[0];
    const int*   mask = (const int*)  d_in[1];
    const float* wq   = (const float*)d_in[2];
    const float* bq   = (const float*)d_in[3];
    const float* wk   = (const float*)d_in[4];
    const float* bk   = (const float*)d_in[5];
    const float* wv   = (const float*)d_in[6];
    const float* bv   = (const float*)d_in[7];
    const float* wo   = (const float*)d_in[8];
    const float* bo   = (const float*)d_in[9];
    const float* w1   = (const float*)d_in[10];
    const float* b1   = (const float*)d_in[11];
    const float* w2   = (const float*)d_in[12];
    const float* b2   = (const float*)d_in[13];
    const float* a1   = (const float*)d_in[14];
    const float* g1   = (const float*)d_in[15];
    const float* a2   = (const float*)d_in[16];
    const float* g2   = (const float*)d_in[17];
    float* out = (float*)d_out;

    float *n_, *qkv_, *ctx_, *x1_, *n2_, *ff1_, *wr_, *bqkv_;
    cudaGetSymbolAddress((void**)&n_,    g_n);
    cudaGetSymbolAddress((void**)&qkv_,  g_qkv);
    cudaGetSymbolAddress((void**)&ctx_,  g_ctx);
    cudaGetSymbolAddress((void**)&x1_,   g_x1);
    cudaGetSymbolAddress((void**)&n2_,   g_n2);
    cudaGetSymbolAddress((void**)&ff1_,  g_ff1);
    cudaGetSymbolAddress((void**)&wr_,   g_wr);
    cudaGetSymbolAddress((void**)&bqkv_, g_bqkv);

    const long DD = (long)D_ * D_;
    float* wqkvr = wr_;                              // [K=1024, 3072]
    float* wor   = wr_ + (long)D_ * D3_;
    float* w1r   = wor + DD;
    float* w2r   = w1r + (long)D_ * DFF_;

    round_qkv_kernel<<<512, 256>>>(wq, wk, wv, bq, bk, bv, wqkvr, bqkv_);
    roundw_kernel<<<512, 256>>>(wo, wor, (int)(DD / 4));
    roundw_kernel<<<512, 256>>>(w1, w1r, (int)((long)D_ * DFF_ / 4));
    roundw_kernel<<<512, 256>>>(w2, w2r, (int)((long)D_ * DFF_ / 4));

    layernorm_kernel<<<M_, 256>>>(x, a1, g1, n_);

    mma_gemm<0,1><<<dim3(D3_ / 128, M_ / 128), 128>>>(
        n_, wqkvr, bqkv_, nullptr, qkv_, M_, D3_, D_, D_, D3_, D3_);

    flash_attn_kernel<<<dim3(S_ / 64, B_ * H_), 128>>>(qkv_, mask, ctx_);

    mma_gemm<2,0><<<dim3(D_ / 128, M_ / 128), 128>>>(
        ctx_, wor, bo, x, x1_, M_, D_, D_, D_, D_, D_);

    layernorm_kernel<<<M_, 256>>>(x1_, a2, g2, n2_);
    mma_gemm<1,1><<<dim3(DFF_ / 128, M_ / 128), 128>>>(
        n2_, w1r, b1, nullptr, ff1_, M_, DFF_, D_, D_, DFF_, DFF_);
    mma_gemm<2,0><<<dim3(D_ / 128, M_ / 128), 128>>>(
        ff1_, w2r, b2, x1_, out, M_, D_, DFF_, DFF_, D_, D_);
}